// round 6
// baseline (speedup 1.0000x reference)
#include <cuda_runtime.h>
#include <cuda_fp16.h>
#include <mma.h>
#include <math.h>

using namespace nvcuda;

#define NMAX 100000
#define EMAX 1600000

// ---------------- device scratch ----------------
__device__ float  g_dinv[NMAX];
__device__ int    g_cnt[NMAX];
__device__ int    g_fill[NMAX];
__device__ int    g_rowptr[NMAX + 1];
__device__ int    g_bsum[256];
__device__ int    g_col[EMAX];
// quantized message buffers + scales
__device__ signed char g_qA[(size_t)NMAX * 128];  // feature msgs (int8)
__device__ float       g_sA[(size_t)NMAX * 2];    // 2 chunks of 64
__device__ signed char g_qC[(size_t)NMAX * 64];   // label msgs (int8)
__device__ float       g_sC[(size_t)NMAX];
// fp16 activation buffers
__device__ __half g_hB[(size_t)NMAX * 128];   // feature agg out
__device__ __half g_hH2[(size_t)NMAX * 128];  // feature final
__device__ __half g_hD[(size_t)NMAX * 64];    // label agg out

// ---------------- CSR build ----------------
__global__ void zero_counts_kernel(int n) {
    int i = blockIdx.x * blockDim.x + threadIdx.x;
    if (i < n) { g_cnt[i] = 0; g_fill[i] = 0; }
}

__global__ void count_edges_kernel(const int* __restrict__ dst, int e) {
    int i = blockIdx.x * blockDim.x + threadIdx.x;
    if (i < e) atomicAdd(&g_cnt[dst[i]], 1);
}

__global__ void scan1_kernel(int n) {
    __shared__ int s[1024];
    int tid = threadIdx.x;
    int i = blockIdx.x * 1024 + tid;
    int v = (i < n) ? g_cnt[i] : 0;
    s[tid] = v;
    __syncthreads();
    for (int off = 1; off < 1024; off <<= 1) {
        int t2 = (tid >= off) ? s[tid - off] : 0;
        __syncthreads();
        s[tid] += t2;
        __syncthreads();
    }
    if (i < n) {
        g_rowptr[i] = s[tid] - v;
        g_dinv[i] = rsqrtf((float)(v + 1));
    }
    if (tid == 1023) g_bsum[blockIdx.x] = s[1023];
}

__global__ void scan2_kernel(int nb) {
    __shared__ int s[128];
    int tid = threadIdx.x;
    int v = (tid < nb) ? g_bsum[tid] : 0;
    s[tid] = v;
    __syncthreads();
    for (int off = 1; off < 128; off <<= 1) {
        int t2 = (tid >= off) ? s[tid - off] : 0;
        __syncthreads();
        s[tid] += t2;
        __syncthreads();
    }
    if (tid < nb) g_bsum[tid] = s[tid] - v;
    if (tid == 127) g_bsum[nb] = s[127];
}

__global__ void scan3_kernel(int n, int nb) {
    int i = blockIdx.x * blockDim.x + threadIdx.x;
    if (i < n) g_rowptr[i] += g_bsum[i >> 10];
    if (i == 0) g_rowptr[n] = g_bsum[nb];
}

__global__ void scatter_edges_kernel(const int* __restrict__ src,
                                     const int* __restrict__ dst, int e) {
    int i = blockIdx.x * blockDim.x + threadIdx.x;
    if (i < e) {
        int d = dst[i];
        int p = g_rowptr[d] + atomicAdd(&g_fill[d], 1);
        g_col[p] = src[i];
    }
}

// ---------------- wmma GEMM ----------------
// EPI 0: A rows pre-scaled by dinv; output int8 quantized per 64-col chunk
//        (scale = absmax/127 into sc_out[row * (C/64) + chunk]).
// EPI 1: output = sigmoid(acc + bias), fp32 (final layer).
#define GBM 128
#define GBN 64

template <int K, int C, int K1, int EPI, typename TA>
__global__ __launch_bounds__(128) void gemm_wmma_kernel(
    const TA* __restrict__ A1, const __half* __restrict__ A2,
    const float* __restrict__ W, const float* __restrict__ bias,
    void* __restrict__ outv, float* __restrict__ sc_out, int n) {
    constexpr int LDW = GBN + 8;   // half
    constexpr int LDA = K + 8;     // half
    constexpr int LDS_ = GBN + 4;  // float staging
    extern __shared__ char smraw[];
    __half* Ws = (__half*)smraw;
    __half* As = (__half*)(smraw + (size_t)K * LDW * 2);
    float*  St = (float*)(smraw + (size_t)K * LDW * 2);

    const int t = threadIdx.x;
    const int w = t >> 5;
    const int row0 = blockIdx.x * GBM;
    const int bn0 = blockIdx.y * GBN;

    for (int idx = t; idx < K * GBN / 4; idx += 128) {
        int k = idx / (GBN / 4);
        int j = (idx % (GBN / 4)) * 4;
        const float* src = W + (size_t)k * C + bn0 + j;
        Ws[k * LDW + j + 0] = __float2half(src[0]);
        Ws[k * LDW + j + 1] = __float2half(src[1]);
        Ws[k * LDW + j + 2] = __float2half(src[2]);
        Ws[k * LDW + j + 3] = __float2half(src[3]);
    }

    constexpr int CPR = K / 8;
#pragma unroll
    for (int it = 0; it < GBM * CPR / 128; it++) {
        int cidx = t + it * 128;
        int r = cidx / CPR;
        int kq = (cidx % CPR) * 8;
        int gr = row0 + r;
        float vals[8];
        if (gr < n) {
            float s = (EPI == 0) ? g_dinv[gr] : 1.0f;
            if (kq < K1) {
                const TA* p = A1 + (size_t)gr * K1 + kq;
#pragma unroll
                for (int q = 0; q < 8; q++) vals[q] = s * (float)p[q];
            } else {
                const __half* p = A2 + (size_t)gr * (K - K1) + (kq - K1);
#pragma unroll
                for (int q = 0; q < 8; q++) vals[q] = s * __half2float(p[q]);
            }
        } else {
#pragma unroll
            for (int q = 0; q < 8; q++) vals[q] = 0.f;
        }
        __half* dstp = As + r * LDA + kq;
#pragma unroll
        for (int q = 0; q < 8; q++) dstp[q] = __float2half(vals[q]);
    }
    __syncthreads();

    wmma::fragment<wmma::accumulator, 16, 16, 16, float> acc[2][4];
#pragma unroll
    for (int i = 0; i < 2; i++)
#pragma unroll
        for (int j = 0; j < 4; j++) wmma::fill_fragment(acc[i][j], 0.f);

    for (int k = 0; k < K; k += 16) {
        wmma::fragment<wmma::matrix_a, 16, 16, 16, __half, wmma::row_major> af[2];
        wmma::fragment<wmma::matrix_b, 16, 16, 16, __half, wmma::row_major> bfr[4];
        wmma::load_matrix_sync(af[0], As + (w * 32 + 0) * LDA + k, LDA);
        wmma::load_matrix_sync(af[1], As + (w * 32 + 16) * LDA + k, LDA);
#pragma unroll
        for (int j = 0; j < 4; j++)
            wmma::load_matrix_sync(bfr[j], Ws + k * LDW + j * 16, LDW);
#pragma unroll
        for (int i = 0; i < 2; i++)
#pragma unroll
            for (int j = 0; j < 4; j++)
                wmma::mma_sync(acc[i][j], af[i], bfr[j], acc[i][j]);
    }

    __syncthreads();
#pragma unroll
    for (int i = 0; i < 2; i++)
#pragma unroll
        for (int j = 0; j < 4; j++)
            wmma::store_matrix_sync(St + (w * 32 + i * 16) * LDS_ + j * 16,
                                    acc[i][j], LDS_, wmma::mem_row_major);
    __syncthreads();

    // epilogue: 128 threads = 16 rows x 8 lanes (8 floats each), 8 row-groups
    const int lane = t & 7;
    const int rsub = t >> 3;
#pragma unroll
    for (int g = 0; g < 8; g++) {
        int r = g * 16 + rsub;
        int gr = row0 + r;
        if (gr >= n) continue;
        const float* sp = St + r * LDS_ + lane * 8;
        float v[8];
#pragma unroll
        for (int q = 0; q < 8; q++) v[q] = sp[q];
        if (EPI == 0) {
            // chunk absmax across the 8 lanes of this row
            float m = 0.f;
#pragma unroll
            for (int q = 0; q < 8; q++) m = fmaxf(m, fabsf(v[q]));
            m = fmaxf(m, __shfl_xor_sync(0xffffffffu, m, 1));
            m = fmaxf(m, __shfl_xor_sync(0xffffffffu, m, 2));
            m = fmaxf(m, __shfl_xor_sync(0xffffffffu, m, 4));
            float inv = (m > 0.f) ? 127.f / m : 0.f;
            union { signed char c[8]; uint2 u; } pk;
#pragma unroll
            for (int q = 0; q < 8; q++)
                pk.c[q] = (signed char)__float2int_rn(v[q] * inv);
            signed char* qout = (signed char*)outv + (size_t)gr * C + bn0 + lane * 8;
            *(uint2*)qout = pk.u;
            if (lane == 0)
                sc_out[(size_t)gr * (C / 64) + (bn0 >> 6)] = m * (1.f / 127.f);
        } else {
            const float* bp = bias + bn0 + lane * 8;
            float ov[8];
#pragma unroll
            for (int q = 0; q < 8; q++)
                ov[q] = 1.f / (1.f + __expf(-(v[q] + bp[q])));
            float* outp = (float*)outv + (size_t)gr * C + bn0 + lane * 8;
            *(float4*)outp = *(float4*)ov;
            *(float4*)(outp + 4) = *(float4*)(ov + 4);
        }
    }
}

// ---------------- aggregation (int8 msgs + scale, fp32 accum, fp16 out) ------
// out[v] = relu?(dinv[v]*(sum_{u in nbr+self} sc[u]*q[u]) + b)
template <int D, bool RELU>
__global__ __launch_bounds__(256) void agg_q_kernel(
    const signed char* __restrict__ qs, const float* __restrict__ sc,
    const float* __restrict__ bias, __half* __restrict__ out, int n) {
    constexpr int LPN = D / 16;      // lanes per node, 16 int8 each
    constexpr int SS = D / 64;       // scale chunks per node
    int idx = blockIdx.x * blockDim.x + threadIdx.x;
    int v = idx / LPN;
    int lane = idx % LPN;
    if (v >= n) return;
    const int c0 = lane * 16;
    const int sub = c0 >> 6;         // which 64-col chunk
    const uint4* base = (const uint4*)qs;

    float acc[16];
    {
        uint4 m = base[(size_t)v * LPN + lane];
        float su = sc[(size_t)v * SS + sub];
        const char4* cp = (const char4*)&m;
#pragma unroll
        for (int w2 = 0; w2 < 4; w2++) {
            char4 cc = cp[w2];
            acc[w2 * 4 + 0] = su * (float)cc.x;
            acc[w2 * 4 + 1] = su * (float)cc.y;
            acc[w2 * 4 + 2] = su * (float)cc.z;
            acc[w2 * 4 + 3] = su * (float)cc.w;
        }
    }
    int beg = g_rowptr[v], end = g_rowptr[v + 1];
    int e = beg;
    for (; e + 1 < end; e += 2) {
        int u0 = g_col[e], u1 = g_col[e + 1];
        uint4 m0 = base[(size_t)u0 * LPN + lane];
        uint4 m1 = base[(size_t)u1 * LPN + lane];
        float s0 = sc[(size_t)u0 * SS + sub];
        float s1 = sc[(size_t)u1 * SS + sub];
        const char4* c0p = (const char4*)&m0;
        const char4* c1p = (const char4*)&m1;
#pragma unroll
        for (int w2 = 0; w2 < 4; w2++) {
            char4 a = c0p[w2], b = c1p[w2];
            acc[w2 * 4 + 0] += s0 * (float)a.x + s1 * (float)b.x;
            acc[w2 * 4 + 1] += s0 * (float)a.y + s1 * (float)b.y;
            acc[w2 * 4 + 2] += s0 * (float)a.z + s1 * (float)b.z;
            acc[w2 * 4 + 3] += s0 * (float)a.w + s1 * (float)b.w;
        }
    }
    if (e < end) {
        int u = g_col[e];
        uint4 m = base[(size_t)u * LPN + lane];
        float su = sc[(size_t)u * SS + sub];
        const char4* cp = (const char4*)&m;
#pragma unroll
        for (int w2 = 0; w2 < 4; w2++) {
            char4 a = cp[w2];
            acc[w2 * 4 + 0] += su * (float)a.x;
            acc[w2 * 4 + 1] += su * (float)a.y;
            acc[w2 * 4 + 2] += su * (float)a.z;
            acc[w2 * 4 + 3] += su * (float)a.w;
        }
    }
    float s = g_dinv[v];
    __half hv[16];
#pragma unroll
    for (int q = 0; q < 16; q++) {
        float r = s * acc[q] + bias[c0 + q];
        if (RELU) r = fmaxf(r, 0.f);
        hv[q] = __float2half(r);
    }
    __half* op = out + (size_t)v * D + c0;
    *(uint4*)op = *(uint4*)hv;
    *(uint4*)(op + 8) = *(uint4*)(hv + 8);
}

// ---------------- host launch ----------------
extern "C" void kernel_launch(void* const* d_in, const int* in_sizes, int n_in,
                              void* d_out, int out_size) {
    const float* x   = (const float*)d_in[0];
    const float* y   = (const float*)d_in[1];
    const int*   ei  = (const int*)d_in[2];
    const float* Wg1 = (const float*)d_in[3];
    const float* bg1 = (const float*)d_in[4];
    const float* Wg2 = (const float*)d_in[5];
    const float* bg2 = (const float*)d_in[6];
    const float* Wl  = (const float*)d_in[7];
    const float* bl  = (const float*)d_in[8];
    const float* Wf  = (const float*)d_in[9];
    const float* bf  = (const float*)d_in[10];
    float* out = (float*)d_out;

    int n = in_sizes[0] / 128;
    int e = in_sizes[2] / 2;
    const int* src = ei;
    const int* dst = ei + e;

    signed char *qA, *qC;
    float *sA, *sC;
    __half *hB, *hH2, *hD;
    cudaGetSymbolAddress((void**)&qA, g_qA);
    cudaGetSymbolAddress((void**)&qC, g_qC);
    cudaGetSymbolAddress((void**)&sA, g_sA);
    cudaGetSymbolAddress((void**)&sC, g_sC);
    cudaGetSymbolAddress((void**)&hB, g_hB);
    cudaGetSymbolAddress((void**)&hH2, g_hH2);
    cudaGetSymbolAddress((void**)&hD, g_hD);

    auto smem_sz = [](int K) -> size_t {
        size_t WsB = (size_t)K * (GBN + 8) * 2;
        size_t AsB = (size_t)GBM * (K + 8) * 2;
        size_t StB = (size_t)GBM * (GBN + 4) * 4;
        return WsB + (AsB > StB ? AsB : StB);
    };
    size_t sm64 = smem_sz(64), sm128 = smem_sz(128), sm192 = smem_sz(192);

    cudaFuncSetAttribute((const void*)gemm_wmma_kernel<128, 128, 128, 0, float>,
                         cudaFuncAttributeMaxDynamicSharedMemorySize, (int)sm128);
    cudaFuncSetAttribute((const void*)gemm_wmma_kernel<128, 128, 128, 0, __half>,
                         cudaFuncAttributeMaxDynamicSharedMemorySize, (int)sm128);
    cudaFuncSetAttribute((const void*)gemm_wmma_kernel<64, 64, 64, 0, float>,
                         cudaFuncAttributeMaxDynamicSharedMemorySize, (int)sm64);
    cudaFuncSetAttribute((const void*)gemm_wmma_kernel<64, 64, 64, 0, __half>,
                         cudaFuncAttributeMaxDynamicSharedMemorySize, (int)sm64);
    cudaFuncSetAttribute((const void*)gemm_wmma_kernel<192, 64, 128, 1, __half>,
                         cudaFuncAttributeMaxDynamicSharedMemorySize, (int)sm192);

    int nb_n = (n + 255) / 256;
    int nb_e = (e + 255) / 256;
    int nb_scan = (n + 1023) / 1024;

    // CSR + dinv
    zero_counts_kernel<<<nb_n, 256>>>(n);
    count_edges_kernel<<<nb_e, 256>>>(dst, e);
    scan1_kernel<<<nb_scan, 1024>>>(n);
    scan2_kernel<<<1, 128>>>(nb_scan);
    scan3_kernel<<<(n + 1023) / 1024, 1024>>>(n, nb_scan);
    scatter_edges_kernel<<<nb_e, 256>>>(src, dst, e);

    int rb = (n + GBM - 1) / GBM;
    dim3 g128(rb, 2);
    dim3 g64(rb, 1);
    int aq128_blocks = (int)(((size_t)n * 8 + 255) / 256);
    int aq64_blocks  = (int)(((size_t)n * 4 + 255) / 256);

    // feature branch
    gemm_wmma_kernel<128, 128, 128, 0, float><<<g128, 128, sm128>>>(
        x, nullptr, Wg1, nullptr, qA, sA, n);
    agg_q_kernel<128, true><<<aq128_blocks, 256>>>(qA, sA, bg1, hB, n);
    gemm_wmma_kernel<128, 128, 128, 0, __half><<<g128, 128, sm128>>>(
        hB, nullptr, Wg2, nullptr, qA, sA, n);
    agg_q_kernel<128, false><<<aq128_blocks, 256>>>(qA, sA, bg2, hH2, n);

    // label branch
    gemm_wmma_kernel<64, 64, 64, 0, float><<<g64, 128, sm64>>>(
        y, nullptr, Wl, nullptr, qC, sC, n);
    agg_q_kernel<64, true><<<aq64_blocks, 256>>>(qC, sC, bl, hD, n);
    for (int j = 1; j < 10; j++) {
        gemm_wmma_kernel<64, 64, 64, 0, __half><<<g64, 128, sm64>>>(
            hD, nullptr, Wl + (size_t)j * 64 * 64, nullptr, qC, sC, n);
        if (j < 9)
            agg_q_kernel<64, true><<<aq64_blocks, 256>>>(
                qC, sC, bl + (size_t)j * 64, hD, n);
        else
            agg_q_kernel<64, false><<<aq64_blocks, 256>>>(
                qC, sC, bl + (size_t)j * 64, hD, n);
    }

    // final fused layer: sigmoid(concat(h2, xl) @ Wf + bf)
    gemm_wmma_kernel<192, 64, 128, 1, __half><<<g64, 128, sm192>>>(
        hH2, hD, Wf, bf, out, nullptr, n);
}

// round 7
// speedup vs baseline: 1.3647x; 1.3647x over previous
#include <cuda_runtime.h>
#include <cuda_fp16.h>
#include <mma.h>
#include <math.h>

using namespace nvcuda;

#define NMAX 100000
#define EMAX 1600000
#define DEGB 512   // degree buckets for counting sort

// ---------------- device scratch ----------------
__device__ float  g_dinv[NMAX];
__device__ int    g_cnt[NMAX];
__device__ int    g_fill[NMAX];
__device__ int    g_rowptr[NMAX + 1];
__device__ int    g_bsum[256];
__device__ int    g_col[EMAX];
__device__ int    g_dhist[DEGB];
__device__ int    g_dfill[DEGB];
__device__ int    g_perm[NMAX];
__device__ __half g_hA[(size_t)NMAX * 128];
__device__ __half g_hB[(size_t)NMAX * 128];
__device__ __half g_hH2[(size_t)NMAX * 128];
__device__ __half g_hD[(size_t)NMAX * 64];

// ---------------- CSR build ----------------
__global__ void zero_counts_kernel(int n) {
    int i = blockIdx.x * blockDim.x + threadIdx.x;
    if (i < n) { g_cnt[i] = 0; g_fill[i] = 0; }
    if (i < DEGB) { g_dhist[i] = 0; g_dfill[i] = 0; }
}

__global__ void count_edges_kernel(const int* __restrict__ dst, int e) {
    int i = blockIdx.x * blockDim.x + threadIdx.x;
    if (i < e) atomicAdd(&g_cnt[dst[i]], 1);
}

// per-block scan of cnt -> local rowptr; block sums; dinv; degree histogram
__global__ void scan1_kernel(int n) {
    __shared__ int s[1024];
    int tid = threadIdx.x;
    int i = blockIdx.x * 1024 + tid;
    int v = (i < n) ? g_cnt[i] : 0;
    s[tid] = v;
    __syncthreads();
    for (int off = 1; off < 1024; off <<= 1) {
        int t2 = (tid >= off) ? s[tid - off] : 0;
        __syncthreads();
        s[tid] += t2;
        __syncthreads();
    }
    if (i < n) {
        g_rowptr[i] = s[tid] - v;
        g_dinv[i] = rsqrtf((float)(v + 1));
        int d = v < DEGB ? v : DEGB - 1;
        atomicAdd(&g_dhist[d], 1);
    }
    if (tid == 1023) g_bsum[blockIdx.x] = s[1023];
}

// scan bsum (<=128) and dhist (512) in one 512-thread block
__global__ void scan2_kernel(int nb) {
    __shared__ int s[512];
    int tid = threadIdx.x;
    // ---- scan bsum ----
    {
        int v = (tid < nb) ? g_bsum[tid] : 0;
        s[tid] = v;
        __syncthreads();
        for (int off = 1; off < 512; off <<= 1) {
            int t2 = (tid >= off) ? s[tid - off] : 0;
            __syncthreads();
            s[tid] += t2;
            __syncthreads();
        }
        if (tid < nb) g_bsum[tid] = s[tid] - v;
        if (tid == 511) g_bsum[nb] = s[511];
        __syncthreads();
    }
    // ---- scan dhist ----
    {
        int v = g_dhist[tid];
        s[tid] = v;
        __syncthreads();
        for (int off = 1; off < 512; off <<= 1) {
            int t2 = (tid >= off) ? s[tid - off] : 0;
            __syncthreads();
            s[tid] += t2;
            __syncthreads();
        }
        g_dhist[tid] = s[tid] - v;  // exclusive
    }
}

__global__ void scan3_kernel(int n, int nb) {
    int i = blockIdx.x * blockDim.x + threadIdx.x;
    if (i < n) g_rowptr[i] += g_bsum[i >> 10];
    if (i == 0) g_rowptr[n] = g_bsum[nb];
}

__global__ void scatter_edges_kernel(const int* __restrict__ src,
                                     const int* __restrict__ dst, int e) {
    int i = blockIdx.x * blockDim.x + threadIdx.x;
    if (i < e) {
        int d = dst[i];
        int p = g_rowptr[d] + atomicAdd(&g_fill[d], 1);
        g_col[p] = src[i];
    }
}

// counting-sort scatter: perm holds node ids ordered by degree
__global__ void perm_kernel(int n) {
    int i = blockIdx.x * blockDim.x + threadIdx.x;
    if (i < n) {
        int c = g_cnt[i];
        int d = c < DEGB ? c : DEGB - 1;
        int pos = g_dhist[d] + atomicAdd(&g_dfill[d], 1);
        g_perm[pos] = i;
    }
}

// ---------------- wmma GEMM ----------------
#define GBM 128
#define GBN 64

template <int K, int C, int K1, int EPI, typename TA>
__global__ __launch_bounds__(128) void gemm_wmma_kernel(
    const TA* __restrict__ A1, const __half* __restrict__ A2,
    const float* __restrict__ W, const float* __restrict__ bias,
    void* __restrict__ outv, int n) {
    constexpr int LDW = GBN + 8;
    constexpr int LDA = K + 8;
    constexpr int LDS_ = GBN + 4;
    extern __shared__ char smraw[];
    __half* Ws = (__half*)smraw;
    __half* As = (__half*)(smraw + (size_t)K * LDW * 2);
    float*  St = (float*)(smraw + (size_t)K * LDW * 2);

    const int t = threadIdx.x;
    const int w = t >> 5;
    const int row0 = blockIdx.x * GBM;
    const int bn0 = blockIdx.y * GBN;

    for (int idx = t; idx < K * GBN / 4; idx += 128) {
        int k = idx / (GBN / 4);
        int j = (idx % (GBN / 4)) * 4;
        const float* src = W + (size_t)k * C + bn0 + j;
        Ws[k * LDW + j + 0] = __float2half(src[0]);
        Ws[k * LDW + j + 1] = __float2half(src[1]);
        Ws[k * LDW + j + 2] = __float2half(src[2]);
        Ws[k * LDW + j + 3] = __float2half(src[3]);
    }

    constexpr int CPR = K / 8;
#pragma unroll
    for (int it = 0; it < GBM * CPR / 128; it++) {
        int cidx = t + it * 128;
        int r = cidx / CPR;
        int kq = (cidx % CPR) * 8;
        int gr = row0 + r;
        float vals[8];
        if (gr < n) {
            float s = (EPI == 0) ? g_dinv[gr] : 1.0f;
            if (kq < K1) {
                const TA* p = A1 + (size_t)gr * K1 + kq;
#pragma unroll
                for (int q = 0; q < 8; q++) vals[q] = s * (float)p[q];
            } else {
                const __half* p = A2 + (size_t)gr * (K - K1) + (kq - K1);
#pragma unroll
                for (int q = 0; q < 8; q++) vals[q] = s * __half2float(p[q]);
            }
        } else {
#pragma unroll
            for (int q = 0; q < 8; q++) vals[q] = 0.f;
        }
        __half* dstp = As + r * LDA + kq;
#pragma unroll
        for (int q = 0; q < 8; q++) dstp[q] = __float2half(vals[q]);
    }
    __syncthreads();

    wmma::fragment<wmma::accumulator, 16, 16, 16, float> acc[2][4];
#pragma unroll
    for (int i = 0; i < 2; i++)
#pragma unroll
        for (int j = 0; j < 4; j++) wmma::fill_fragment(acc[i][j], 0.f);

    for (int k = 0; k < K; k += 16) {
        wmma::fragment<wmma::matrix_a, 16, 16, 16, __half, wmma::row_major> af[2];
        wmma::fragment<wmma::matrix_b, 16, 16, 16, __half, wmma::row_major> bfr[4];
        wmma::load_matrix_sync(af[0], As + (w * 32 + 0) * LDA + k, LDA);
        wmma::load_matrix_sync(af[1], As + (w * 32 + 16) * LDA + k, LDA);
#pragma unroll
        for (int j = 0; j < 4; j++)
            wmma::load_matrix_sync(bfr[j], Ws + k * LDW + j * 16, LDW);
#pragma unroll
        for (int i = 0; i < 2; i++)
#pragma unroll
            for (int j = 0; j < 4; j++)
                wmma::mma_sync(acc[i][j], af[i], bfr[j], acc[i][j]);
    }

    __syncthreads();
#pragma unroll
    for (int i = 0; i < 2; i++)
#pragma unroll
        for (int j = 0; j < 4; j++)
            wmma::store_matrix_sync(St + (w * 32 + i * 16) * LDS_ + j * 16,
                                    acc[i][j], LDS_, wmma::mem_row_major);
    __syncthreads();

    const int lane = t & 7;
    const int rsub = t >> 3;
#pragma unroll
    for (int g = 0; g < 8; g++) {
        int r = g * 16 + rsub;
        int gr = row0 + r;
        if (gr >= n) continue;
        const float* sp = St + r * LDS_ + lane * 8;
        if (EPI == 0) {
            __half* outp = (__half*)outv + (size_t)gr * C + bn0 + lane * 8;
            __half hv[8];
#pragma unroll
            for (int q = 0; q < 8; q++) hv[q] = __float2half(sp[q]);
            *(uint4*)outp = *(uint4*)hv;
        } else {
            float* outp = (float*)outv + (size_t)gr * C + bn0 + lane * 8;
            const float* bp = bias + bn0 + lane * 8;
            float ov[8];
#pragma unroll
            for (int q = 0; q < 8; q++)
                ov[q] = 1.f / (1.f + __expf(-(sp[q] + bp[q])));
            *(float4*)outp = *(float4*)ov;
            *(float4*)(outp + 4) = *(float4*)(ov + 4);
        }
    }
}

// ---------------- aggregation (degree-sorted order, 4x unrolled) ----------
template <int D, bool RELU>
__global__ __launch_bounds__(256) void agg_kernel(
    const __half* __restrict__ hs, const float* __restrict__ bias,
    __half* __restrict__ out, int n) {
    constexpr int LPN = D / 8;  // lanes per node, 8 halfs each
    int idx = blockIdx.x * blockDim.x + threadIdx.x;
    int grp = idx / LPN;
    int lane = idx % LPN;
    if (grp >= n) return;
    int v = g_perm[grp];        // degree-sorted node id
    int c = lane * 8;
    const uint4* base = (const uint4*)hs;
    size_t selfidx = ((size_t)v * D + c) >> 3;

    float acc[8];
    {
        uint4 sv = base[selfidx];
        const __half2* h = (const __half2*)&sv;
#pragma unroll
        for (int q = 0; q < 4; q++) {
            float2 f = __half22float2(h[q]);
            acc[2 * q] = f.x; acc[2 * q + 1] = f.y;
        }
    }
    int beg = g_rowptr[v], end = g_rowptr[v + 1];
    int e = beg;
    for (; e + 3 < end; e += 4) {
        int u0 = g_col[e], u1 = g_col[e + 1], u2 = g_col[e + 2], u3 = g_col[e + 3];
        uint4 m0 = base[((size_t)u0 * D + c) >> 3];
        uint4 m1 = base[((size_t)u1 * D + c) >> 3];
        uint4 m2 = base[((size_t)u2 * D + c) >> 3];
        uint4 m3 = base[((size_t)u3 * D + c) >> 3];
        const __half2* h0 = (const __half2*)&m0;
        const __half2* h1 = (const __half2*)&m1;
        const __half2* h2 = (const __half2*)&m2;
        const __half2* h3 = (const __half2*)&m3;
#pragma unroll
        for (int q = 0; q < 4; q++) {
            float2 f0 = __half22float2(h0[q]);
            float2 f1 = __half22float2(h1[q]);
            float2 f2 = __half22float2(h2[q]);
            float2 f3 = __half22float2(h3[q]);
            acc[2 * q]     += (f0.x + f1.x) + (f2.x + f3.x);
            acc[2 * q + 1] += (f0.y + f1.y) + (f2.y + f3.y);
        }
    }
    for (; e < end; e++) {
        int u = g_col[e];
        uint4 m = base[((size_t)u * D + c) >> 3];
        const __half2* h = (const __half2*)&m;
#pragma unroll
        for (int q = 0; q < 4; q++) {
            float2 f = __half22float2(h[q]);
            acc[2 * q] += f.x;
            acc[2 * q + 1] += f.y;
        }
    }
    float s = g_dinv[v];
    float4 b0 = *(const float4*)(bias + c);
    float4 b1 = *(const float4*)(bias + c + 4);
    float bb[8] = {b0.x, b0.y, b0.z, b0.w, b1.x, b1.y, b1.z, b1.w};
    __half hv[8];
#pragma unroll
    for (int q = 0; q < 8; q++) {
        float r = s * acc[q] + bb[q];
        if (RELU) r = fmaxf(r, 0.f);
        hv[q] = __float2half(r);
    }
    ((uint4*)out)[selfidx] = *(uint4*)hv;
}

// ---------------- host launch ----------------
extern "C" void kernel_launch(void* const* d_in, const int* in_sizes, int n_in,
                              void* d_out, int out_size) {
    const float* x   = (const float*)d_in[0];
    const float* y   = (const float*)d_in[1];
    const int*   ei  = (const int*)d_in[2];
    const float* Wg1 = (const float*)d_in[3];
    const float* bg1 = (const float*)d_in[4];
    const float* Wg2 = (const float*)d_in[5];
    const float* bg2 = (const float*)d_in[6];
    const float* Wl  = (const float*)d_in[7];
    const float* bl  = (const float*)d_in[8];
    const float* Wf  = (const float*)d_in[9];
    const float* bf  = (const float*)d_in[10];
    float* out = (float*)d_out;

    int n = in_sizes[0] / 128;
    int e = in_sizes[2] / 2;
    const int* src = ei;
    const int* dst = ei + e;

    __half *hA, *hB, *hH2, *hD;
    cudaGetSymbolAddress((void**)&hA, g_hA);
    cudaGetSymbolAddress((void**)&hB, g_hB);
    cudaGetSymbolAddress((void**)&hH2, g_hH2);
    cudaGetSymbolAddress((void**)&hD, g_hD);

    auto smem_sz = [](int K) -> size_t {
        size_t WsB = (size_t)K * (GBN + 8) * 2;
        size_t AsB = (size_t)GBM * (K + 8) * 2;
        size_t StB = (size_t)GBM * (GBN + 4) * 4;
        return WsB + (AsB > StB ? AsB : StB);
    };
    size_t sm64 = smem_sz(64), sm128 = smem_sz(128), sm192 = smem_sz(192);

    cudaFuncSetAttribute((const void*)gemm_wmma_kernel<128, 128, 128, 0, float>,
                         cudaFuncAttributeMaxDynamicSharedMemorySize, (int)sm128);
    cudaFuncSetAttribute((const void*)gemm_wmma_kernel<128, 128, 128, 0, __half>,
                         cudaFuncAttributeMaxDynamicSharedMemorySize, (int)sm128);
    cudaFuncSetAttribute((const void*)gemm_wmma_kernel<64, 64, 64, 0, float>,
                         cudaFuncAttributeMaxDynamicSharedMemorySize, (int)sm64);
    cudaFuncSetAttribute((const void*)gemm_wmma_kernel<64, 64, 64, 0, __half>,
                         cudaFuncAttributeMaxDynamicSharedMemorySize, (int)sm64);
    cudaFuncSetAttribute((const void*)gemm_wmma_kernel<192, 64, 128, 1, __half>,
                         cudaFuncAttributeMaxDynamicSharedMemorySize, (int)sm192);

    int nb_n = (n + 255) / 256;
    int nb_e = (e + 255) / 256;
    int nb_scan = (n + 1023) / 1024;

    // CSR + dinv + degree sort
    zero_counts_kernel<<<nb_n, 256>>>(n);
    count_edges_kernel<<<nb_e, 256>>>(dst, e);
    scan1_kernel<<<nb_scan, 1024>>>(n);
    scan2_kernel<<<1, 512>>>(nb_scan);
    scan3_kernel<<<(n + 1023) / 1024, 1024>>>(n, nb_scan);
    scatter_edges_kernel<<<nb_e, 256>>>(src, dst, e);
    perm_kernel<<<nb_n, 256>>>(n);

    int rb = (n + GBM - 1) / GBM;
    dim3 g128(rb, 2);
    dim3 g64(rb, 1);
    int agg128_blocks = (int)(((size_t)n * 16 + 255) / 256);
    int agg64_blocks  = (int)(((size_t)n * 8 + 255) / 256);

    // feature branch
    gemm_wmma_kernel<128, 128, 128, 0, float><<<g128, 128, sm128>>>(
        x, nullptr, Wg1, nullptr, hA, n);
    agg_kernel<128, true><<<agg128_blocks, 256>>>(hA, bg1, hB, n);
    gemm_wmma_kernel<128, 128, 128, 0, __half><<<g128, 128, sm128>>>(
        hB, nullptr, Wg2, nullptr, hA, n);
    agg_kernel<128, false><<<agg128_blocks, 256>>>(hA, bg2, hH2, n);

    // label branch
    gemm_wmma_kernel<64, 64, 64, 0, float><<<g64, 128, sm64>>>(
        y, nullptr, Wl, nullptr, hA, n);
    agg_kernel<64, true><<<agg64_blocks, 256>>>(hA, bl, hD, n);
    for (int j = 1; j < 10; j++) {
        gemm_wmma_kernel<64, 64, 64, 0, __half><<<g64, 128, sm64>>>(
            hD, nullptr, Wl + (size_t)j * 64 * 64, nullptr, hA, n);
        if (j < 9)
            agg_kernel<64, true><<<agg64_blocks, 256>>>(
                hA, bl + (size_t)j * 64, hD, n);
        else
            agg_kernel<64, false><<<agg64_blocks, 256>>>(
                hA, bl + (size_t)j * 64, hD, n);
    }

    // final fused layer: sigmoid(concat(h2, xl) @ Wf + bf)
    gemm_wmma_kernel<192, 64, 128, 1, __half><<<g64, 128, sm192>>>(
        hH2, hD, Wf, bf, out, n);
}

// round 9
// speedup vs baseline: 1.5448x; 1.1320x over previous
#include <cuda_runtime.h>
#include <cuda_fp16.h>
#include <mma.h>
#include <math.h>

using namespace nvcuda;

#define NMAX 100000
#define EMAX 1600000

// ---------------- device scratch ----------------
__device__ float  g_dinv[NMAX];
__device__ int    g_cnt[NMAX];
__device__ int    g_fill[NMAX];
__device__ int    g_rowptr[NMAX + 1];
__device__ int    g_bsum[256];
__device__ int    g_col[EMAX];
__device__ __half g_hA[(size_t)NMAX * 128];
__device__ __half g_hB[(size_t)NMAX * 128];
__device__ __half g_hH2[(size_t)NMAX * 128];
__device__ __half g_hD[(size_t)NMAX * 64];

// ---------------- CSR build ----------------
__global__ void zero_counts_kernel(int n) {
    int i = blockIdx.x * blockDim.x + threadIdx.x;
    if (i < n) { g_cnt[i] = 0; g_fill[i] = 0; }
}

__global__ void count_edges_kernel(const int* __restrict__ dst, int e) {
    int i = blockIdx.x * blockDim.x + threadIdx.x;
    if (i < e) atomicAdd(&g_cnt[dst[i]], 1);
}

__global__ void scan1_kernel(int n) {
    __shared__ int s[1024];
    int tid = threadIdx.x;
    int i = blockIdx.x * 1024 + tid;
    int v = (i < n) ? g_cnt[i] : 0;
    s[tid] = v;
    __syncthreads();
    for (int off = 1; off < 1024; off <<= 1) {
        int t2 = (tid >= off) ? s[tid - off] : 0;
        __syncthreads();
        s[tid] += t2;
        __syncthreads();
    }
    if (i < n) {
        g_rowptr[i] = s[tid] - v;
        g_dinv[i] = rsqrtf((float)(v + 1));
    }
    if (tid == 1023) g_bsum[blockIdx.x] = s[1023];
}

__global__ void scan2_kernel(int nb) {
    __shared__ int s[128];
    int tid = threadIdx.x;
    int v = (tid < nb) ? g_bsum[tid] : 0;
    s[tid] = v;
    __syncthreads();
    for (int off = 1; off < 128; off <<= 1) {
        int t2 = (tid >= off) ? s[tid - off] : 0;
        __syncthreads();
        s[tid] += t2;
        __syncthreads();
    }
    if (tid < nb) g_bsum[tid] = s[tid] - v;
    if (tid == 127) g_bsum[nb] = s[127];
}

__global__ void scan3_kernel(int n, int nb) {
    int i = blockIdx.x * blockDim.x + threadIdx.x;
    if (i < n) g_rowptr[i] += g_bsum[i >> 10];
    if (i == 0) g_rowptr[n] = g_bsum[nb];
}

__global__ void scatter_edges_kernel(const int* __restrict__ src,
                                     const int* __restrict__ dst, int e) {
    int i = blockIdx.x * blockDim.x + threadIdx.x;
    if (i < e) {
        int d = dst[i];
        int p = g_rowptr[d] + atomicAdd(&g_fill[d], 1);
        g_col[p] = src[i];
    }
}

// ---------------- wmma GEMM (vectorized loads) ----------------
#define GBM 128
#define GBN 64

template <int K, int C, int K1, int EPI, typename TA>
__global__ __launch_bounds__(128) void gemm_wmma_kernel(
    const TA* __restrict__ A1, const __half* __restrict__ A2,
    const float* __restrict__ W, const float* __restrict__ bias,
    void* __restrict__ outv, int n) {
    constexpr int LDW = GBN + 8;   // halves
    constexpr int LDA = K + 8;     // halves
    constexpr int LDS_ = GBN + 4;  // floats
    extern __shared__ char smraw[];
    __half* Ws = (__half*)smraw;
    __half* As = (__half*)(smraw + (size_t)K * LDW * 2);
    float*  St = (float*)(smraw + (size_t)K * LDW * 2);

    const int t = threadIdx.x;
    const int w = t >> 5;
    const int row0 = blockIdx.x * GBM;
    const int bn0 = blockIdx.y * GBN;

    // load W tile [K][BN]: float4 loads, packed half2 x2 store (8B)
    for (int idx = t; idx < K * GBN / 4; idx += 128) {
        int k = idx / (GBN / 4);
        int j = (idx % (GBN / 4)) * 4;
        float4 wv = *(const float4*)(W + (size_t)k * C + bn0 + j);
        uint2 pk;
        __half2* h = (__half2*)&pk;
        h[0] = __floats2half2_rn(wv.x, wv.y);
        h[1] = __floats2half2_rn(wv.z, wv.w);
        *(uint2*)&Ws[k * LDW + j] = pk;
    }

    // load A tile [BM][K], pre-scaled by dinv when EPI==0
    constexpr int CPR = K / 8;  // 8-half chunks per row
#pragma unroll
    for (int it = 0; it < GBM * CPR / 128; it++) {
        int cidx = t + it * 128;
        int r = cidx / CPR;
        int kq = (cidx % CPR) * 8;
        int gr = row0 + r;
        uint4 pk = make_uint4(0, 0, 0, 0);
        if (gr < n) {
            float s = (EPI == 0) ? g_dinv[gr] : 1.0f;
            __half2 s2 = __float2half2_rn(s);
            if (kq < K1) {
                if (sizeof(TA) == 2) {  // half source: uint4 load + half2 scale
                    uint4 raw = *(const uint4*)((const __half*)A1 +
                                                (size_t)gr * K1 + kq);
                    __half2* h = (__half2*)&raw;
                    if (EPI == 0) {
#pragma unroll
                        for (int q = 0; q < 4; q++) h[q] = __hmul2(h[q], s2);
                    }
                    pk = raw;
                } else {  // float source: two float4 loads
                    const float* p = (const float*)A1 + (size_t)gr * K1 + kq;
                    float4 a = *(const float4*)p;
                    float4 b = *(const float4*)(p + 4);
                    __half2* h = (__half2*)&pk;
                    h[0] = __floats2half2_rn(s * a.x, s * a.y);
                    h[1] = __floats2half2_rn(s * a.z, s * a.w);
                    h[2] = __floats2half2_rn(s * b.x, s * b.y);
                    h[3] = __floats2half2_rn(s * b.z, s * b.w);
                }
            } else {
                uint4 raw = *(const uint4*)(A2 + (size_t)gr * (K - K1) +
                                            (kq - K1));
                __half2* h = (__half2*)&raw;
                if (EPI == 0) {
#pragma unroll
                    for (int q = 0; q < 4; q++) h[q] = __hmul2(h[q], s2);
                }
                pk = raw;
            }
        }
        *(uint4*)&As[r * LDA + kq] = pk;
    }
    __syncthreads();

    wmma::fragment<wmma::accumulator, 16, 16, 16, float> acc[2][4];
#pragma unroll
    for (int i = 0; i < 2; i++)
#pragma unroll
        for (int j = 0; j < 4; j++) wmma::fill_fragment(acc[i][j], 0.f);

    for (int k = 0; k < K; k += 16) {
        wmma::fragment<wmma::matrix_a, 16, 16, 16, __half, wmma::row_major> af[2];
        wmma::fragment<wmma::matrix_b, 16, 16, 16, __half, wmma::row_major> bfr[4];
        wmma::load_matrix_sync(af[0], As + (w * 32 + 0) * LDA + k, LDA);
        wmma::load_matrix_sync(af[1], As + (w * 32 + 16) * LDA + k, LDA);
#pragma unroll
        for (int j = 0; j < 4; j++)
            wmma::load_matrix_sync(bfr[j], Ws + k * LDW + j * 16, LDW);
#pragma unroll
        for (int i = 0; i < 2; i++)
#pragma unroll
            for (int j = 0; j < 4; j++)
                wmma::mma_sync(acc[i][j], af[i], bfr[j], acc[i][j]);
    }

    __syncthreads();
#pragma unroll
    for (int i = 0; i < 2; i++)
#pragma unroll
        for (int j = 0; j < 4; j++)
            wmma::store_matrix_sync(St + (w * 32 + i * 16) * LDS_ + j * 16,
                                    acc[i][j], LDS_, wmma::mem_row_major);
    __syncthreads();

    const int lane = t & 7;
    const int rsub = t >> 3;
#pragma unroll
    for (int g = 0; g < 8; g++) {
        int r = g * 16 + rsub;
        int gr = row0 + r;
        if (gr >= n) continue;
        const float* sp = St + r * LDS_ + lane * 8;
        if (EPI == 0) {
            uint4 pk;
            __half2* h = (__half2*)&pk;
            h[0] = __floats2half2_rn(sp[0], sp[1]);
            h[1] = __floats2half2_rn(sp[2], sp[3]);
            h[2] = __floats2half2_rn(sp[4], sp[5]);
            h[3] = __floats2half2_rn(sp[6], sp[7]);
            *(uint4*)((__half*)outv + (size_t)gr * C + bn0 + lane * 8) = pk;
        } else {
            float* outp = (float*)outv + (size_t)gr * C + bn0 + lane * 8;
            const float* bp = bias + bn0 + lane * 8;
            float ov[8];
#pragma unroll
            for (int q = 0; q < 8; q++)
                ov[q] = 1.f / (1.f + __expf(-(sp[q] + bp[q])));
            *(float4*)outp = *(float4*)ov;
            *(float4*)(outp + 4) = *(float4*)(ov + 4);
        }
    }
}

// ---------------- aggregation (fp16 msgs, fp32 accum, 4x unroll) ----------
template <int D, bool RELU>
__global__ __launch_bounds__(256) void agg_kernel(
    const __half* __restrict__ hs, const float* __restrict__ bias,
    __half* __restrict__ out, int n) {
    constexpr int LPN = D / 8;  // lanes per node, 8 halfs each
    int idx = blockIdx.x * blockDim.x + threadIdx.x;
    int v = idx / LPN;
    int lane = idx % LPN;
    if (v >= n) return;
    int c = lane * 8;
    const uint4* base = (const uint4*)hs;
    size_t selfidx = ((size_t)v * D + c) >> 3;

    float acc[8];
    {
        uint4 sv = base[selfidx];
        const __half2* h = (const __half2*)&sv;
#pragma unroll
        for (int q = 0; q < 4; q++) {
            float2 f = __half22float2(h[q]);
            acc[2 * q] = f.x; acc[2 * q + 1] = f.y;
        }
    }
    int beg = g_rowptr[v], end = g_rowptr[v + 1];
    int e = beg;
    for (; e + 3 < end; e += 4) {
        int u0 = g_col[e], u1 = g_col[e + 1], u2 = g_col[e + 2], u3 = g_col[e + 3];
        uint4 m0 = base[((size_t)u0 * D + c) >> 3];
        uint4 m1 = base[((size_t)u1 * D + c) >> 3];
        uint4 m2 = base[((size_t)u2 * D + c) >> 3];
        uint4 m3 = base[((size_t)u3 * D + c) >> 3];
        const __half2* h0 = (const __half2*)&m0;
        const __half2* h1 = (const __half2*)&m1;
        const __half2* h2 = (const __half2*)&m2;
        const __half2* h3 = (const __half2*)&m3;
#pragma unroll
        for (int q = 0; q < 4; q++) {
            float2 f0 = __half22float2(h0[q]);
            float2 f1 = __half22float2(h1[q]);
            float2 f2 = __half22float2(h2[q]);
            float2 f3 = __half22float2(h3[q]);
            acc[2 * q]     += (f0.x + f1.x) + (f2.x + f3.x);
            acc[2 * q + 1] += (f0.y + f1.y) + (f2.y + f3.y);
        }
    }
    for (; e < end; e++) {
        int u = g_col[e];
        uint4 m = base[((size_t)u * D + c) >> 3];
        const __half2* h = (const __half2*)&m;
#pragma unroll
        for (int q = 0; q < 4; q++) {
            float2 f = __half22float2(h[q]);
            acc[2 * q] += f.x;
            acc[2 * q + 1] += f.y;
        }
    }
    float s = g_dinv[v];
    float4 b0 = *(const float4*)(bias + c);
    float4 b1 = *(const float4*)(bias + c + 4);
    float bb[8] = {b0.x, b0.y, b0.z, b0.w, b1.x, b1.y, b1.z, b1.w};
    uint4 pk;
    __half2* hv = (__half2*)&pk;
#pragma unroll
    for (int q = 0; q < 4; q++) {
        float r0 = s * acc[2 * q] + bb[2 * q];
        float r1 = s * acc[2 * q + 1] + bb[2 * q + 1];
        if (RELU) { r0 = fmaxf(r0, 0.f); r1 = fmaxf(r1, 0.f); }
        hv[q] = __floats2half2_rn(r0, r1);
    }
    ((uint4*)out)[selfidx] = pk;
}

// ---------------- host launch ----------------
extern "C" void kernel_launch(void* const* d_in, const int* in_sizes, int n_in,
                              void* d_out, int out_size) {
    const float* x   = (const float*)d_in[0];
    const float* y   = (const float*)d_in[1];
    const int*   ei  = (const int*)d_in[2];
    const float* Wg1 = (const float*)d_in[3];
    const float* bg1 = (const float*)d_in[4];
    const float* Wg2 = (const float*)d_in[5];
    const float* bg2 = (const float*)d_in[6];
    const float* Wl  = (const float*)d_in[7];
    const float* bl  = (const float*)d_in[8];
    const float* Wf  = (const float*)d_in[9];
    const float* bf  = (const float*)d_in[10];
    float* out = (float*)d_out;

    int n = in_sizes[0] / 128;
    int e = in_sizes[2] / 2;
    const int* src = ei;
    const int* dst = ei + e;

    __half *hA, *hB, *hH2, *hD;
    cudaGetSymbolAddress((void**)&hA, g_hA);
    cudaGetSymbolAddress((void**)&hB, g_hB);
    cudaGetSymbolAddress((void**)&hH2, g_hH2);
    cudaGetSymbolAddress((void**)&hD, g_hD);

    auto smem_sz = [](int K) -> size_t {
        size_t WsB = (size_t)K * (GBN + 8) * 2;
        size_t AsB = (size_t)GBM * (K + 8) * 2;
        size_t StB = (size_t)GBM * (GBN + 4) * 4;
        return WsB + (AsB > StB ? AsB : StB);
    };
    size_t sm64 = smem_sz(64), sm128 = smem_sz(128), sm192 = smem_sz(192);

    cudaFuncSetAttribute((const void*)gemm_wmma_kernel<128, 128, 128, 0, float>,
                         cudaFuncAttributeMaxDynamicSharedMemorySize, (int)sm128);
    cudaFuncSetAttribute((const void*)gemm_wmma_kernel<128, 128, 128, 0, __half>,
                         cudaFuncAttributeMaxDynamicSharedMemorySize, (int)sm128);
    cudaFuncSetAttribute((const void*)gemm_wmma_kernel<64, 64, 64, 0, float>,
                         cudaFuncAttributeMaxDynamicSharedMemorySize, (int)sm64);
    cudaFuncSetAttribute((const void*)gemm_wmma_kernel<64, 64, 64, 0, __half>,
                         cudaFuncAttributeMaxDynamicSharedMemorySize, (int)sm64);
    cudaFuncSetAttribute((const void*)gemm_wmma_kernel<192, 64, 128, 1, __half>,
                         cudaFuncAttributeMaxDynamicSharedMemorySize, (int)sm192);

    int nb_n = (n + 255) / 256;
    int nb_e = (e + 255) / 256;
    int nb_scan = (n + 1023) / 1024;

    // CSR + dinv
    zero_counts_kernel<<<nb_n, 256>>>(n);
    count_edges_kernel<<<nb_e, 256>>>(dst, e);
    scan1_kernel<<<nb_scan, 1024>>>(n);
    scan2_kernel<<<1, 128>>>(nb_scan);
    scan3_kernel<<<(n + 1023) / 1024, 1024>>>(n, nb_scan);
    scatter_edges_kernel<<<nb_e, 256>>>(src, dst, e);

    int rb = (n + GBM - 1) / GBM;
    dim3 g128(rb, 2);
    dim3 g64(rb, 1);
    int agg128_blocks = (int)(((size_t)n * 16 + 255) / 256);
    int agg64_blocks  = (int)(((size_t)n * 8 + 255) / 256);

    // feature branch
    gemm_wmma_kernel<128, 128, 128, 0, float><<<g128, 128, sm128>>>(
        x, nullptr, Wg1, nullptr, hA, n);
    agg_kernel<128, true><<<agg128_blocks, 256>>>(hA, bg1, hB, n);
    gemm_wmma_kernel<128, 128, 128, 0, __half><<<g128, 128, sm128>>>(
        hB, nullptr, Wg2, nullptr, hA, n);
    agg_kernel<128, false><<<agg128_blocks, 256>>>(hA, bg2, hH2, n);

    // label branch
    gemm_wmma_kernel<64, 64, 64, 0, float><<<g64, 128, sm64>>>(
        y, nullptr, Wl, nullptr, hA, n);
    agg_kernel<64, true><<<agg64_blocks, 256>>>(hA, bl, hD, n);
    for (int j = 1; j < 10; j++) {
        gemm_wmma_kernel<64, 64, 64, 0, __half><<<g64, 128, sm64>>>(
            hD, nullptr, Wl + (size_t)j * 64 * 64, nullptr, hA, n);
        if (j < 9)
            agg_kernel<64, true><<<agg64_blocks, 256>>>(
                hA, bl + (size_t)j * 64, hD, n);
        else
            agg_kernel<64, false><<<agg64_blocks, 256>>>(
                hA, bl + (size_t)j * 64, hD, n);
    }

    // final fused layer: sigmoid(concat(h2, xl) @ Wf + bf)
    gemm_wmma_kernel<192, 64, 128, 1, __half><<<g64, 128, sm192>>>(
        hH2, hD, Wf, bf, out, n);
}

// round 10
// speedup vs baseline: 1.5791x; 1.0222x over previous
#include <cuda_runtime.h>
#include <cuda_fp16.h>
#include <mma.h>
#include <math.h>

using namespace nvcuda;

#define NMAX 100000
#define EMAX 1600000

// ---------------- device scratch ----------------
__device__ float  g_dinv[NMAX];
__device__ int    g_cnt[NMAX];
__device__ int    g_fill[NMAX];
__device__ int    g_rowptr[NMAX + 1];
__device__ int    g_bsum[256];
__device__ int    g_col[EMAX];
__device__ __half g_hA[(size_t)NMAX * 128];
__device__ __half g_hB[(size_t)NMAX * 128];
__device__ __half g_hH2[(size_t)NMAX * 128];
__device__ __half g_hD[(size_t)NMAX * 64];

// ---------------- CSR build ----------------
__global__ void zero_counts_kernel(int n) {
    int i = blockIdx.x * blockDim.x + threadIdx.x;
    if (i < n) { g_cnt[i] = 0; g_fill[i] = 0; }
}

__global__ void count_edges_kernel(const int* __restrict__ dst, int e) {
    int i = blockIdx.x * blockDim.x + threadIdx.x;
    if (i < e) atomicAdd(&g_cnt[dst[i]], 1);
}

__global__ void scan1_kernel(int n) {
    __shared__ int s[1024];
    int tid = threadIdx.x;
    int i = blockIdx.x * 1024 + tid;
    int v = (i < n) ? g_cnt[i] : 0;
    s[tid] = v;
    __syncthreads();
    for (int off = 1; off < 1024; off <<= 1) {
        int t2 = (tid >= off) ? s[tid - off] : 0;
        __syncthreads();
        s[tid] += t2;
        __syncthreads();
    }
    if (i < n) {
        g_rowptr[i] = s[tid] - v;
        g_dinv[i] = rsqrtf((float)(v + 1));
    }
    if (tid == 1023) g_bsum[blockIdx.x] = s[1023];
}

__global__ void scan2_kernel(int nb) {
    __shared__ int s[128];
    int tid = threadIdx.x;
    int v = (tid < nb) ? g_bsum[tid] : 0;
    s[tid] = v;
    __syncthreads();
    for (int off = 1; off < 128; off <<= 1) {
        int t2 = (tid >= off) ? s[tid - off] : 0;
        __syncthreads();
        s[tid] += t2;
        __syncthreads();
    }
    if (tid < nb) g_bsum[tid] = s[tid] - v;
    if (tid == 127) g_bsum[nb] = s[127];
}

__global__ void scan3_kernel(int n, int nb) {
    int i = blockIdx.x * blockDim.x + threadIdx.x;
    if (i < n) g_rowptr[i] += g_bsum[i >> 10];
    if (i == 0) g_rowptr[n] = g_bsum[nb];
}

__global__ void scatter_edges_kernel(const int* __restrict__ src,
                                     const int* __restrict__ dst, int e) {
    int i = blockIdx.x * blockDim.x + threadIdx.x;
    if (i < e) {
        int d = dst[i];
        int p = g_rowptr[d] + atomicAdd(&g_fill[d], 1);
        g_col[p] = src[i];
    }
}

// ---------------- wmma GEMM (vectorized loads) ----------------
#define GBM 128
#define GBN 64

template <int K, int C, int K1, int EPI, typename TA>
__global__ __launch_bounds__(128) void gemm_wmma_kernel(
    const TA* __restrict__ A1, const __half* __restrict__ A2,
    const float* __restrict__ W, const float* __restrict__ bias,
    void* __restrict__ outv, int n) {
    constexpr int LDW = GBN + 8;   // halves
    constexpr int LDA = K + 8;     // halves
    constexpr int LDS_ = GBN + 4;  // floats
    extern __shared__ char smraw[];
    __half* Ws = (__half*)smraw;
    __half* As = (__half*)(smraw + (size_t)K * LDW * 2);
    float*  St = (float*)(smraw + (size_t)K * LDW * 2);

    const int t = threadIdx.x;
    const int w = t >> 5;
    const int row0 = blockIdx.x * GBM;
    const int bn0 = blockIdx.y * GBN;

    // load W tile [K][BN]: float4 loads, packed half2 x2 store (8B)
    for (int idx = t; idx < K * GBN / 4; idx += 128) {
        int k = idx / (GBN / 4);
        int j = (idx % (GBN / 4)) * 4;
        float4 wv = *(const float4*)(W + (size_t)k * C + bn0 + j);
        uint2 pk;
        __half2* h = (__half2*)&pk;
        h[0] = __floats2half2_rn(wv.x, wv.y);
        h[1] = __floats2half2_rn(wv.z, wv.w);
        *(uint2*)&Ws[k * LDW + j] = pk;
    }

    // load A tile [BM][K], pre-scaled by dinv when EPI==0
    constexpr int CPR = K / 8;  // 8-half chunks per row
#pragma unroll
    for (int it = 0; it < GBM * CPR / 128; it++) {
        int cidx = t + it * 128;
        int r = cidx / CPR;
        int kq = (cidx % CPR) * 8;
        int gr = row0 + r;
        uint4 pk = make_uint4(0, 0, 0, 0);
        if (gr < n) {
            float s = (EPI == 0) ? g_dinv[gr] : 1.0f;
            __half2 s2 = __float2half2_rn(s);
            if (kq < K1) {
                if (sizeof(TA) == 2) {  // half source: uint4 load + half2 scale
                    uint4 raw = *(const uint4*)((const __half*)A1 +
                                                (size_t)gr * K1 + kq);
                    __half2* h = (__half2*)&raw;
                    if (EPI == 0) {
#pragma unroll
                        for (int q = 0; q < 4; q++) h[q] = __hmul2(h[q], s2);
                    }
                    pk = raw;
                } else {  // float source: two float4 loads
                    const float* p = (const float*)A1 + (size_t)gr * K1 + kq;
                    float4 a = *(const float4*)p;
                    float4 b = *(const float4*)(p + 4);
                    __half2* h = (__half2*)&pk;
                    h[0] = __floats2half2_rn(s * a.x, s * a.y);
                    h[1] = __floats2half2_rn(s * a.z, s * a.w);
                    h[2] = __floats2half2_rn(s * b.x, s * b.y);
                    h[3] = __floats2half2_rn(s * b.z, s * b.w);
                }
            } else {
                uint4 raw = *(const uint4*)(A2 + (size_t)gr * (K - K1) +
                                            (kq - K1));
                __half2* h = (__half2*)&raw;
                if (EPI == 0) {
#pragma unroll
                    for (int q = 0; q < 4; q++) h[q] = __hmul2(h[q], s2);
                }
                pk = raw;
            }
        }
        *(uint4*)&As[r * LDA + kq] = pk;
    }
    __syncthreads();

    wmma::fragment<wmma::accumulator, 16, 16, 16, float> acc[2][4];
#pragma unroll
    for (int i = 0; i < 2; i++)
#pragma unroll
        for (int j = 0; j < 4; j++) wmma::fill_fragment(acc[i][j], 0.f);

    for (int k = 0; k < K; k += 16) {
        wmma::fragment<wmma::matrix_a, 16, 16, 16, __half, wmma::row_major> af[2];
        wmma::fragment<wmma::matrix_b, 16, 16, 16, __half, wmma::row_major> bfr[4];
        wmma::load_matrix_sync(af[0], As + (w * 32 + 0) * LDA + k, LDA);
        wmma::load_matrix_sync(af[1], As + (w * 32 + 16) * LDA + k, LDA);
#pragma unroll
        for (int j = 0; j < 4; j++)
            wmma::load_matrix_sync(bfr[j], Ws + k * LDW + j * 16, LDW);
#pragma unroll
        for (int i = 0; i < 2; i++)
#pragma unroll
            for (int j = 0; j < 4; j++)
                wmma::mma_sync(acc[i][j], af[i], bfr[j], acc[i][j]);
    }

    __syncthreads();
#pragma unroll
    for (int i = 0; i < 2; i++)
#pragma unroll
        for (int j = 0; j < 4; j++)
            wmma::store_matrix_sync(St + (w * 32 + i * 16) * LDS_ + j * 16,
                                    acc[i][j], LDS_, wmma::mem_row_major);
    __syncthreads();

    const int lane = t & 7;
    const int rsub = t >> 3;
#pragma unroll
    for (int g = 0; g < 8; g++) {
        int r = g * 16 + rsub;
        int gr = row0 + r;
        if (gr >= n) continue;
        const float* sp = St + r * LDS_ + lane * 8;
        if (EPI == 0) {
            uint4 pk;
            __half2* h = (__half2*)&pk;
            h[0] = __floats2half2_rn(sp[0], sp[1]);
            h[1] = __floats2half2_rn(sp[2], sp[3]);
            h[2] = __floats2half2_rn(sp[4], sp[5]);
            h[3] = __floats2half2_rn(sp[6], sp[7]);
            *(uint4*)((__half*)outv + (size_t)gr * C + bn0 + lane * 8) = pk;
        } else {
            float* outp = (float*)outv + (size_t)gr * C + bn0 + lane * 8;
            const float* bp = bias + bn0 + lane * 8;
            float ov[8];
#pragma unroll
            for (int q = 0; q < 8; q++)
                ov[q] = 1.f / (1.f + __expf(-(sp[q] + bp[q])));
            *(float4*)outp = *(float4*)ov;
            *(float4*)(outp + 4) = *(float4*)(ov + 4);
        }
    }
}

// ---------------- aggregation: half2 4-edge tree + fp32 running sum ----------
template <int D, bool RELU>
__global__ __launch_bounds__(256) void agg_kernel(
    const __half* __restrict__ hs, const float* __restrict__ bias,
    __half* __restrict__ out, int n) {
    constexpr int LPN = D / 8;  // lanes per node, 8 halfs each
    int idx = blockIdx.x * blockDim.x + threadIdx.x;
    int v = idx / LPN;
    int lane = idx % LPN;
    if (v >= n) return;
    int c = lane * 8;
    const uint4* base = (const uint4*)hs;
    size_t selfidx = ((size_t)v * D + c) >> 3;

    float acc[8];
    {
        uint4 sv = base[selfidx];
        const __half2* h = (const __half2*)&sv;
#pragma unroll
        for (int q = 0; q < 4; q++) {
            float2 f = __half22float2(h[q]);
            acc[2 * q] = f.x; acc[2 * q + 1] = f.y;
        }
    }
    int beg = g_rowptr[v], end = g_rowptr[v + 1];
    int e = beg;
    for (; e + 3 < end; e += 4) {
        int u0 = g_col[e], u1 = g_col[e + 1], u2 = g_col[e + 2], u3 = g_col[e + 3];
        uint4 m0 = base[((size_t)u0 * D + c) >> 3];
        uint4 m1 = base[((size_t)u1 * D + c) >> 3];
        uint4 m2 = base[((size_t)u2 * D + c) >> 3];
        uint4 m3 = base[((size_t)u3 * D + c) >> 3];
        const __half2* h0 = (const __half2*)&m0;
        const __half2* h1 = (const __half2*)&m1;
        const __half2* h2 = (const __half2*)&m2;
        const __half2* h3 = (const __half2*)&m3;
#pragma unroll
        for (int q = 0; q < 4; q++) {
            // 4-value tree sum in half2 (error ~2^-10, << fp16 storage noise)
            __half2 tq = __hadd2(__hadd2(h0[q], h1[q]), __hadd2(h2[q], h3[q]));
            float2 f = __half22float2(tq);
            acc[2 * q] += f.x;
            acc[2 * q + 1] += f.y;
        }
    }
    for (; e < end; e++) {
        int u = g_col[e];
        uint4 m = base[((size_t)u * D + c) >> 3];
        const __half2* h = (const __half2*)&m;
#pragma unroll
        for (int q = 0; q < 4; q++) {
            float2 f = __half22float2(h[q]);
            acc[2 * q] += f.x;
            acc[2 * q + 1] += f.y;
        }
    }
    float s = g_dinv[v];
    float4 b0 = *(const float4*)(bias + c);
    float4 b1 = *(const float4*)(bias + c + 4);
    float bb[8] = {b0.x, b0.y, b0.z, b0.w, b1.x, b1.y, b1.z, b1.w};
    uint4 pk;
    __half2* hv = (__half2*)&pk;
#pragma unroll
    for (int q = 0; q < 4; q++) {
        float r0 = s * acc[2 * q] + bb[2 * q];
        float r1 = s * acc[2 * q + 1] + bb[2 * q + 1];
        if (RELU) { r0 = fmaxf(r0, 0.f); r1 = fmaxf(r1, 0.f); }
        hv[q] = __floats2half2_rn(r0, r1);
    }
    ((uint4*)out)[selfidx] = pk;
}

// ---------------- host launch ----------------
extern "C" void kernel_launch(void* const* d_in, const int* in_sizes, int n_in,
                              void* d_out, int out_size) {
    const float* x   = (const float*)d_in[0];
    const float* y   = (const float*)d_in[1];
    const int*   ei  = (const int*)d_in[2];
    const float* Wg1 = (const float*)d_in[3];
    const float* bg1 = (const float*)d_in[4];
    const float* Wg2 = (const float*)d_in[5];
    const float* bg2 = (const float*)d_in[6];
    const float* Wl  = (const float*)d_in[7];
    const float* bl  = (const float*)d_in[8];
    const float* Wf  = (const float*)d_in[9];
    const float* bf  = (const float*)d_in[10];
    float* out = (float*)d_out;

    int n = in_sizes[0] / 128;
    int e = in_sizes[2] / 2;
    const int* src = ei;
    const int* dst = ei + e;

    __half *hA, *hB, *hH2, *hD;
    cudaGetSymbolAddress((void**)&hA, g_hA);
    cudaGetSymbolAddress((void**)&hB, g_hB);
    cudaGetSymbolAddress((void**)&hH2, g_hH2);
    cudaGetSymbolAddress((void**)&hD, g_hD);

    auto smem_sz = [](int K) -> size_t {
        size_t WsB = (size_t)K * (GBN + 8) * 2;
        size_t AsB = (size_t)GBM * (K + 8) * 2;
        size_t StB = (size_t)GBM * (GBN + 4) * 4;
        return WsB + (AsB > StB ? AsB : StB);
    };
    size_t sm64 = smem_sz(64), sm128 = smem_sz(128), sm192 = smem_sz(192);

    cudaFuncSetAttribute((const void*)gemm_wmma_kernel<128, 128, 128, 0, float>,
                         cudaFuncAttributeMaxDynamicSharedMemorySize, (int)sm128);
    cudaFuncSetAttribute((const void*)gemm_wmma_kernel<128, 128, 128, 0, __half>,
                         cudaFuncAttributeMaxDynamicSharedMemorySize, (int)sm128);
    cudaFuncSetAttribute((const void*)gemm_wmma_kernel<64, 64, 64, 0, float>,
                         cudaFuncAttributeMaxDynamicSharedMemorySize, (int)sm64);
    cudaFuncSetAttribute((const void*)gemm_wmma_kernel<64, 64, 64, 0, __half>,
                         cudaFuncAttributeMaxDynamicSharedMemorySize, (int)sm64);
    cudaFuncSetAttribute((const void*)gemm_wmma_kernel<192, 64, 128, 1, __half>,
                         cudaFuncAttributeMaxDynamicSharedMemorySize, (int)sm192);

    int nb_n = (n + 255) / 256;
    int nb_e = (e + 255) / 256;
    int nb_scan = (n + 1023) / 1024;

    // CSR + dinv
    zero_counts_kernel<<<nb_n, 256>>>(n);
    count_edges_kernel<<<nb_e, 256>>>(dst, e);
    scan1_kernel<<<nb_scan, 1024>>>(n);
    scan2_kernel<<<1, 128>>>(nb_scan);
    scan3_kernel<<<(n + 1023) / 1024, 1024>>>(n, nb_scan);
    scatter_edges_kernel<<<nb_e, 256>>>(src, dst, e);

    int rb = (n + GBM - 1) / GBM;
    dim3 g128(rb, 2);
    dim3 g64(rb, 1);
    int agg128_blocks = (int)(((size_t)n * 16 + 255) / 256);
    int agg64_blocks  = (int)(((size_t)n * 8 + 255) / 256);

    // feature branch
    gemm_wmma_kernel<128, 128, 128, 0, float><<<g128, 128, sm128>>>(
        x, nullptr, Wg1, nullptr, hA, n);
    agg_kernel<128, true><<<agg128_blocks, 256>>>(hA, bg1, hB, n);
    gemm_wmma_kernel<128, 128, 128, 0, __half><<<g128, 128, sm128>>>(
        hB, nullptr, Wg2, nullptr, hA, n);
    agg_kernel<128, false><<<agg128_blocks, 256>>>(hA, bg2, hH2, n);

    // label branch
    gemm_wmma_kernel<64, 64, 64, 0, float><<<g64, 128, sm64>>>(
        y, nullptr, Wl, nullptr, hA, n);
    agg_kernel<64, true><<<agg64_blocks, 256>>>(hA, bl, hD, n);
    for (int j = 1; j < 10; j++) {
        gemm_wmma_kernel<64, 64, 64, 0, __half><<<g64, 128, sm64>>>(
            hD, nullptr, Wl + (size_t)j * 64 * 64, nullptr, hA, n);
        if (j < 9)
            agg_kernel<64, true><<<agg64_blocks, 256>>>(
                hA, bl + (size_t)j * 64, hD, n);
        else
            agg_kernel<64, false><<<agg64_blocks, 256>>>(
                hA, bl + (size_t)j * 64, hD, n);
    }

    // final fused layer: sigmoid(concat(h2, xl) @ Wf + bf)
    gemm_wmma_kernel<192, 64, 128, 1, __half><<<g64, 128, sm192>>>(
        hH2, hD, Wf, bf, out, n);
}